// round 8
// baseline (speedup 1.0000x reference)
#include <cuda_runtime.h>

// Problem constants (fixed by dataset: B=2, N=512, E=128, H=8, D=16)
#define B_    2
#define N_    512
#define E_    128
#define H_    8
#define D_    16
#define ROWS_ (B_ * N_)   // 1024

// ---------------- packed fp32x2 helpers (Blackwell FFMA2/FADD2) -------------
typedef unsigned long long u64;
#define ABS2_MASK 0x7fffffff7fffffffULL

__device__ __forceinline__ u64 pack2(float lo, float hi) {
    u64 r; asm("mov.b64 %0, {%1, %2};" : "=l"(r) : "f"(lo), "f"(hi)); return r;
}
__device__ __forceinline__ float2 unpk2(u64 v) {
    float2 f; asm("mov.b64 {%0, %1}, %2;" : "=f"(f.x), "=f"(f.y) : "l"(v)); return f;
}
__device__ __forceinline__ u64 ffma2(u64 a, u64 b, u64 c) {
    u64 d; asm("fma.rn.f32x2 %0, %1, %2, %3;" : "=l"(d) : "l"(a), "l"(b), "l"(c)); return d;
}
__device__ __forceinline__ u64 fadd2(u64 a, u64 b) {
    u64 d; asm("add.rn.f32x2 %0, %1, %2;" : "=l"(d) : "l"(a), "l"(b)); return d;
}

// Butterfly transpose-reduce over 16 per-lane partials: returns, on lane L,
// the full 32-lane sum of pc[bitrev4(L & 15)].
__device__ __forceinline__ float butterfly16(float* pc, int lane) {
    #pragma unroll
    for (int r = 0; r < 4; r++) {
        const int half = 8 >> r;
        const bool hi = (lane >> r) & 1;
        #pragma unroll
        for (int j = 0; j < 8; j++) {
            if (j < half) {
                float send = hi ? pc[j] : pc[j + half];
                float keep = hi ? pc[j + half] : pc[j];
                float recv = __shfl_xor_sync(0xffffffffu, send, 1 << r);
                pc[j] = keep + recv;
            }
        }
    }
    return pc[0] + __shfl_xor_sync(0xffffffffu, pc[0], 16);
}
__device__ __forceinline__ int bitrev4(int l) {
    return ((l & 1) << 3) | (((l >> 1) & 1) << 2)
         | (((l >> 2) & 1) << 1) | ((l >> 3) & 1);
}

// ---------------------------------------------------------------------------
// Single fused kernel: per-(b,n) CTA computes its own q,v (warp GEMV),
// edge-conditioned attention (packed f32x2, bound-B single-pass softmax),
// and output projection. warp = head; 16 m per lane.
//
//   lrelu(em*w + b) = 0.505(em*w + b) + 0.495|w|*|em + b/w|
//   s[m]  = c0 + c1*em + sum_d g_d |em + r_d|        (affine part folded)
//   p[m]  = exp(s[m] - B),  B = sum_d |q_d| max(|b_d|,|w_d+b_d|) >= max s
//   hat_d = v_d + [0.505(wv_d*S1 + bv_d*Z) + 0.495|wv_d| sum_m p|em+rv_d|]/Z
// ---------------------------------------------------------------------------
__global__ __launch_bounds__(256, 3) void fused_kernel(const float* __restrict__ x,
                                                       const float* __restrict__ e,
                                                       const float* __restrict__ w_qkv,
                                                       const float* __restrict__ w_ekv,
                                                       const float* __restrict__ b_ekv,
                                                       const float* __restrict__ w_prj,
                                                       const float* __restrict__ b_prj,
                                                       float* __restrict__ out) {
    __shared__ float e_s[N_];
    __shared__ float q_s[128], v_s[128];
    __shared__ float wk_s[128], bk_s[128], wv_s[128], bv_s[128];
    __shared__ float hat_s[128];

    const int row  = blockIdx.x;     // b*N + n
    const int tid  = threadIdx.x;
    const int lane = tid & 31;
    const int h    = tid >> 5;       // warp == head

    // ---- stage e + edge params (block-cooperative) ----
    ((float2*)e_s)[tid] = ((const float2*)(e + row * N_))[tid];
    if (tid < 128) {
        wk_s[tid] = w_ekv[tid];
        bk_s[tid] = b_ekv[tid];
    } else {
        int t = tid - 128;
        wv_s[t] = w_ekv[128 + t];
        bv_s[t] = b_ekv[128 + t];
    }

    // ---- in-CTA q,v: warp GEMV over this row's x (L1-resident weights) ----
    {
        float4 x4 = ((const float4*)(x + row * 128))[lane];   // x[lane*4..+3]
        float pc[16];
        #pragma unroll
        for (int i = 0; i < 16; i++) {
            const float4 wq = *(const float4*)&w_qkv[(h * 16 + i) * 128 + lane * 4];
            pc[i] = fmaf(x4.x, wq.x, fmaf(x4.y, wq.y, fmaf(x4.z, wq.z, x4.w * wq.w)));
        }
        float qv = butterfly16(pc, lane);
        if (lane < 16) q_s[h * 16 + bitrev4(lane)] = 0.25f * qv;   // 1/sqrt(D)

        #pragma unroll
        for (int i = 0; i < 16; i++) {
            const float4 wv = *(const float4*)&w_qkv[(256 + h * 16 + i) * 128 + lane * 4];
            pc[i] = fmaf(x4.x, wv.x, fmaf(x4.y, wv.y, fmaf(x4.z, wv.z, x4.w * wv.w)));
        }
        float vv = butterfly16(pc, lane);
        if (lane < 16) v_s[h * 16 + bitrev4(lane)] = vv;
    }
    __syncthreads();

    // ---- per-head packed params (K and V) ----
    u64 r2[8], g2[8], rv2[8], acc2[8];
    float c0 = 0.f, c1 = 0.f;
    {
        float B = 0.f;
        #pragma unroll
        for (int dd = 0; dd < 8; dd++) {
            float2 w = ((const float2*)wk_s)[h * 8 + dd];
            float2 b = ((const float2*)bk_s)[h * 8 + dd];
            float2 q = ((const float2*)q_s)[h * 8 + dd];
            r2[dd] = pack2(__fdividef(b.x, w.x), __fdividef(b.y, w.y));
            g2[dd] = pack2(0.495f * q.x * fabsf(w.x), 0.495f * q.y * fabsf(w.y));
            c1 = fmaf(q.x, w.x, fmaf(q.y, w.y, c1));
            c0 = fmaf(q.x, b.x, fmaf(q.y, b.y, c0));
            B  = fmaf(fabsf(q.x), fmaxf(fabsf(b.x), fabsf(w.x + b.x)),
                 fmaf(fabsf(q.y), fmaxf(fabsf(b.y), fabsf(w.y + b.y)), B));
        }
        c1 *= 0.505f; c0 = 0.505f * c0 - B;   // fold softmax bound
        #pragma unroll
        for (int dd = 0; dd < 8; dd++) {
            float2 w = ((const float2*)wv_s)[h * 8 + dd];
            float2 b = ((const float2*)bv_s)[h * 8 + dd];
            rv2[dd] = pack2(__fdividef(b.x, w.x), __fdividef(b.y, w.y));
            acc2[dd] = 0ULL;
        }
    }

    // ---- fused m-loop: scores -> p -> V accumulation, single pass ----
    float Z = 0.f, S1 = 0.f;
    #pragma unroll
    for (int i = 0; i < 16; i++) {
        const float em = e_s[i * 32 + lane];
        const u64 em2 = pack2(em, em);
        u64 a2 = 0ULL;
        #pragma unroll
        for (int dd = 0; dd < 8; dd++) {
            u64 u2 = fadd2(em2, r2[dd]);
            a2 = ffma2(g2[dd], u2 & ABS2_MASK, a2);
        }
        float2 f = unpk2(a2);
        float p = __expf(fmaf(c1, em, c0) + f.x + f.y);
        Z += p;
        S1 = fmaf(p, em, S1);
        const u64 p2 = pack2(p, p);
        #pragma unroll
        for (int dd = 0; dd < 8; dd++) {
            u64 u2 = fadd2(em2, rv2[dd]);
            acc2[dd] = ffma2(p2, u2 & ABS2_MASK, acc2[dd]);
        }
    }
    #pragma unroll
    for (int k = 16; k >= 1; k >>= 1) {
        Z  += __shfl_xor_sync(0xffffffffu, Z, k);
        S1 += __shfl_xor_sync(0xffffffffu, S1, k);
    }
    const float invZ = 1.f / Z;

    // ---- reduce acc over m-lanes; epilogue hat ----
    float acc[16];
    #pragma unroll
    for (int dd = 0; dd < 8; dd++) {
        float2 fb = unpk2(acc2[dd]);
        acc[2 * dd]     = fb.x;
        acc[2 * dd + 1] = fb.y;
    }
    float tot = butterfly16(acc, lane);
    if (lane < 16) {
        int d = bitrev4(lane);
        float wvd = wv_s[h * 16 + d], bvd = bv_s[h * 16 + d];
        float lin = 0.505f * fmaf(wvd, S1, bvd * Z);
        hat_s[h * 16 + d] = v_s[h * 16 + d]
                          + fmaf(0.495f * fabsf(wvd), tot, lin) * invZ;
    }
    __syncthreads();

    // ---- projection: warp h -> cols [h*16, h*16+16) ----
    {
        float4 h4 = ((const float4*)hat_s)[lane];
        float pc[16];
        #pragma unroll
        for (int i = 0; i < 16; i++) {
            const int c = h * 16 + i;
            float4 wv = *(const float4*)&w_prj[c * 128 + lane * 4];
            pc[i] = fmaf(h4.x, wv.x, fmaf(h4.y, wv.y, fmaf(h4.z, wv.z, h4.w * wv.w)));
        }
        float cval = butterfly16(pc, lane);
        if (lane < 16) {
            const int c = h * 16 + bitrev4(lane);
            out[row * 128 + c] = cval + b_prj[c];
        }
    }
}

// ---------------------------------------------------------------------------
extern "C" void kernel_launch(void* const* d_in, const int* in_sizes, int n_in,
                              void* d_out, int out_size) {
    const float* x     = (const float*)d_in[0];
    const float* e     = (const float*)d_in[1];
    const float* w_qkv = (const float*)d_in[2];
    const float* w_ekv = (const float*)d_in[3];
    const float* b_ekv = (const float*)d_in[4];
    const float* w_prj = (const float*)d_in[5];
    const float* b_prj = (const float*)d_in[6];
    float* out = (float*)d_out;

    fused_kernel<<<ROWS_, 256>>>(x, e, w_qkv, w_ekv, b_ekv, w_prj, b_prj, out);
}

// round 9
// speedup vs baseline: 1.0737x; 1.0737x over previous
#include <cuda_runtime.h>

// Problem constants (fixed by dataset: B=2, N=512, E=128, H=8, D=16)
#define B_    2
#define N_    512
#define E_    128
#define H_    8
#define D_    16
#define ROWS_ (B_ * N_)   // 1024

// Scratch (device globals: allocation-free rule)
__device__ float g_q[ROWS_ * E_];    // q * 0.25 (1/sqrt(D))
__device__ float g_v[ROWS_ * E_];

// ---------------- packed fp32x2 helpers (Blackwell FFMA2/FADD2) -------------
typedef unsigned long long u64;
#define ABS2_MASK 0x7fffffff7fffffffULL

__device__ __forceinline__ u64 pack2(float lo, float hi) {
    u64 r; asm("mov.b64 %0, {%1, %2};" : "=l"(r) : "f"(lo), "f"(hi)); return r;
}
__device__ __forceinline__ float2 unpk2(u64 v) {
    float2 f; asm("mov.b64 {%0, %1}, %2;" : "=f"(f.x), "=f"(f.y) : "l"(v)); return f;
}
__device__ __forceinline__ u64 ffma2(u64 a, u64 b, u64 c) {
    u64 d; asm("fma.rn.f32x2 %0, %1, %2, %3;" : "=l"(d) : "l"(a), "l"(b), "l"(c)); return d;
}
__device__ __forceinline__ u64 fadd2(u64 a, u64 b) {
    u64 d; asm("add.rn.f32x2 %0, %1, %2;" : "=l"(d) : "l"(a), "l"(b)); return d;
}

// ---------------------------------------------------------------------------
// qv GEMM: C[32r x 64c] = X[32 x 128] @ W[64 x 128]^T per CTA (measured 3.7us;
// identical to Round 5).
// ---------------------------------------------------------------------------
#define QV_SMEM_BYTES (32 * 128 * 4 + 128 * 68 * 4)

__global__ __launch_bounds__(128) void qv_kernel(const float* __restrict__ x,
                                                 const float* __restrict__ w_qkv) {
    extern __shared__ float sm[];
    float (*x_s)[128] = (float(*)[128])sm;
    float (*w_s)[68]  = (float(*)[68])(sm + 32 * 128);

    const int tid  = threadIdx.x;
    const int row0 = blockIdx.y * 32;
    const int st   = blockIdx.x;                           // 0,1 -> q ; 2,3 -> v
    const int wbase = (st < 2) ? st * 64 : 128 + st * 64;  // 0,64,256,320
    const float* w_rows = w_qkv + wbase * 128;

    {
        const float4* x4 = (const float4*)(x + row0 * 128);
        float4* xs4 = (float4*)x_s;
        #pragma unroll
        for (int i = 0; i < 8; i++) xs4[tid + i * 128] = x4[tid + i * 128];
    }
    #pragma unroll
    for (int i = 0; i < 64; i++) {
        int idx = tid + i * 128;
        int j = idx & 127, c = idx >> 7;
        w_s[j][c] = w_rows[c * 128 + j];
    }
    __syncthreads();

    const int tx = tid & 15;
    const int ty = tid >> 4;
    float acc[4][4];
    #pragma unroll
    for (int r = 0; r < 4; r++)
        #pragma unroll
        for (int c = 0; c < 4; c++) acc[r][c] = 0.f;

    #pragma unroll 4
    for (int jb = 0; jb < 32; jb++) {
        float4 xr[4], wv[4];
        #pragma unroll
        for (int r = 0; r < 4; r++) xr[r] = *(const float4*)&x_s[ty * 4 + r][jb * 4];
        #pragma unroll
        for (int k = 0; k < 4; k++) wv[k] = *(const float4*)&w_s[jb * 4 + k][tx * 4];
        #pragma unroll
        for (int k = 0; k < 4; k++) {
            float xk[4] = {xr[0].x, xr[1].x, xr[2].x, xr[3].x};
            if (k == 1) { xk[0] = xr[0].y; xk[1] = xr[1].y; xk[2] = xr[2].y; xk[3] = xr[3].y; }
            if (k == 2) { xk[0] = xr[0].z; xk[1] = xr[1].z; xk[2] = xr[2].z; xk[3] = xr[3].z; }
            if (k == 3) { xk[0] = xr[0].w; xk[1] = xr[1].w; xk[2] = xr[2].w; xk[3] = xr[3].w; }
            #pragma unroll
            for (int r = 0; r < 4; r++) {
                acc[r][0] = fmaf(xk[r], wv[k].x, acc[r][0]);
                acc[r][1] = fmaf(xk[r], wv[k].y, acc[r][1]);
                acc[r][2] = fmaf(xk[r], wv[k].z, acc[r][2]);
                acc[r][3] = fmaf(xk[r], wv[k].w, acc[r][3]);
            }
        }
    }

    const float scale = (st < 2) ? 0.25f : 1.0f;
    float* dst = (st < 2) ? g_q : g_v;
    const int cg = (st & 1) * 64 + tx * 4;
    #pragma unroll
    for (int r = 0; r < 4; r++) {
        float4 o = {acc[r][0] * scale, acc[r][1] * scale, acc[r][2] * scale, acc[r][3] * scale};
        *(float4*)&dst[(row0 + ty * 4 + r) * 128 + cg] = o;
    }
}

// ---------------------------------------------------------------------------
// Fused attention + projection — EXACT Round-5 structure (22.0us measured)
// with two surgical ILP fixes:
//   (1) phase-1 accumulator split into two chains (dep depth 8 -> 4)
//   (2) e_s prefetched one iteration ahead in both inner loops
// Everything else (two-pass softmax, scalar e_s, reparam, butterflies,
// projection epilogue) is unchanged from Round 5.
// ---------------------------------------------------------------------------
__global__ __launch_bounds__(256, 3) void attn_proj_kernel(const float* __restrict__ e,
                                                           const float* __restrict__ w_ekv,
                                                           const float* __restrict__ b_ekv,
                                                           const float* __restrict__ w_prj,
                                                           const float* __restrict__ b_prj,
                                                           float* __restrict__ out) {
    __shared__ float e_s[N_];
    __shared__ float q_s[128], v_s[128];
    __shared__ float wk_s[128], bk_s[128], wv_s[128], bv_s[128];
    __shared__ float hat_s[128];

    const int row  = blockIdx.x;     // b*N + n
    const int tid  = threadIdx.x;
    const int lane = tid & 31;
    const int h    = tid >> 5;       // warp == head

    if (tid < 128)
        ((float4*)e_s)[tid] = ((const float4*)(e + row * N_))[tid];
    if (tid < 128) {
        q_s[tid]  = g_q[row * 128 + tid];
        v_s[tid]  = g_v[row * 128 + tid];
        wk_s[tid] = w_ekv[tid];
        bk_s[tid] = b_ekv[tid];
    } else {
        int t = tid - 128;
        wv_s[t] = w_ekv[128 + t];
        bv_s[t] = b_ekv[128 + t];
    }
    __syncthreads();

    float s[16];

    // ======== phase 1: scores (dual accumulator chains + e prefetch) ========
    {
        u64 r2[8], g2[8];
        float c0 = 0.f, c1 = 0.f;
        #pragma unroll
        for (int dd = 0; dd < 8; dd++) {
            float2 w = ((const float2*)wk_s)[h * 8 + dd];
            float2 b = ((const float2*)bk_s)[h * 8 + dd];
            float2 q = ((const float2*)q_s)[h * 8 + dd];
            r2[dd] = pack2(__fdividef(b.x, w.x), __fdividef(b.y, w.y));
            g2[dd] = pack2(0.495f * q.x * fabsf(w.x), 0.495f * q.y * fabsf(w.y));
            c1 = fmaf(q.x, w.x, fmaf(q.y, w.y, c1));
            c0 = fmaf(q.x, b.x, fmaf(q.y, b.y, c0));
        }
        c1 *= 0.505f; c0 *= 0.505f;

        float em = e_s[lane];
        #pragma unroll
        for (int i = 0; i < 16; i++) {
            const float em_cur = em;
            if (i < 15) em = e_s[(i + 1) * 32 + lane];   // prefetch next
            const u64 em2 = pack2(em_cur, em_cur);
            u64 acc2a = 0ULL, acc2b = 0ULL;              // two chains
            #pragma unroll
            for (int dd = 0; dd < 8; dd += 2) {
                u64 ua = fadd2(em2, r2[dd]);
                u64 ub = fadd2(em2, r2[dd + 1]);
                acc2a = ffma2(g2[dd],     ua & ABS2_MASK, acc2a);
                acc2b = ffma2(g2[dd + 1], ub & ABS2_MASK, acc2b);
            }
            float2 f = unpk2(fadd2(acc2a, acc2b));
            s[i] = fmaf(c1, em_cur, c0) + f.x + f.y;
        }
    }

    // ======== softmax over m (+ S1 = sum p*em) — unchanged from R5 ========
    float mx = s[0];
    #pragma unroll
    for (int i = 1; i < 16; i++) mx = fmaxf(mx, s[i]);
    #pragma unroll
    for (int k = 16; k >= 1; k >>= 1) mx = fmaxf(mx, __shfl_xor_sync(0xffffffffu, mx, k));
    float Z = 0.f, S1 = 0.f;
    #pragma unroll
    for (int i = 0; i < 16; i++) {
        s[i] = __expf(s[i] - mx);
        Z += s[i];
        S1 = fmaf(s[i], e_s[i * 32 + lane], S1);
    }
    #pragma unroll
    for (int k = 16; k >= 1; k >>= 1) {
        Z  += __shfl_xor_sync(0xffffffffu, Z, k);
        S1 += __shfl_xor_sync(0xffffffffu, S1, k);
    }
    const float invZ = 1.f / Z;

    // ======== phase 2: acc_d = sum_m p |em + bv_d/wv_d| (8 indep chains) ====
    float acc[16];
    {
        u64 rv2[8], acc2[8];
        #pragma unroll
        for (int dd = 0; dd < 8; dd++) {
            float2 w = ((const float2*)wv_s)[h * 8 + dd];
            float2 b = ((const float2*)bv_s)[h * 8 + dd];
            rv2[dd] = pack2(__fdividef(b.x, w.x), __fdividef(b.y, w.y));
            acc2[dd] = 0ULL;
        }
        float em = e_s[lane];
        #pragma unroll
        for (int i = 0; i < 16; i++) {
            const float em_cur = em;
            if (i < 15) em = e_s[(i + 1) * 32 + lane];   // prefetch next
            const u64 em2 = pack2(em_cur, em_cur);
            const u64 p2  = pack2(s[i], s[i]);
            #pragma unroll
            for (int dd = 0; dd < 8; dd++) {
                u64 u2 = fadd2(em2, rv2[dd]);
                acc2[dd] = ffma2(p2, u2 & ABS2_MASK, acc2[dd]);
            }
        }
        #pragma unroll
        for (int dd = 0; dd < 8; dd++) {
            float2 fb = unpk2(acc2[dd]);
            acc[2 * dd]     = fb.x;
            acc[2 * dd + 1] = fb.y;
        }
    }

    // ---- butterfly transpose-reduce: lane L ends with d = bitrev4(L&15) ----
    #pragma unroll
    for (int r = 0; r < 4; r++) {
        const int half = 8 >> r;
        const bool hi = (lane >> r) & 1;
        #pragma unroll
        for (int j = 0; j < 8; j++) {
            if (j < half) {
                float send = hi ? acc[j] : acc[j + half];
                float keep = hi ? acc[j + half] : acc[j];
                float recv = __shfl_xor_sync(0xffffffffu, send, 1 << r);
                acc[j] = keep + recv;
            }
        }
    }
    float tot = acc[0] + __shfl_xor_sync(0xffffffffu, acc[0], 16);
    if (lane < 16) {
        int d = ((lane & 1) << 3) | (((lane >> 1) & 1) << 2)
              | (((lane >> 2) & 1) << 1) | ((lane >> 3) & 1);
        float wvd = wv_s[h * 16 + d], bvd = bv_s[h * 16 + d];
        float lin = 0.505f * fmaf(wvd, S1, bvd * Z);
        hat_s[h * 16 + d] = v_s[h * 16 + d]
                          + fmaf(0.495f * fabsf(wvd), tot, lin) * invZ;
    }
    __syncthreads();

    // ======== fused projection: warp h -> cols [h*16, h*16+16) ========
    {
        float4 h4 = ((const float4*)hat_s)[lane];   // hat[lane*4 .. +3]
        float pc[16];
        #pragma unroll
        for (int i = 0; i < 16; i++) {
            const int c = h * 16 + i;
            float4 wv = *(const float4*)&w_prj[c * 128 + lane * 4];
            pc[i] = fmaf(h4.x, wv.x, fmaf(h4.y, wv.y, fmaf(h4.z, wv.z, h4.w * wv.w)));
        }
        #pragma unroll
        for (int r = 0; r < 4; r++) {
            const int half = 8 >> r;
            const bool hi = (lane >> r) & 1;
            #pragma unroll
            for (int j = 0; j < 8; j++) {
                if (j < half) {
                    float send = hi ? pc[j] : pc[j + half];
                    float keep = hi ? pc[j + half] : pc[j];
                    float recv = __shfl_xor_sync(0xffffffffu, send, 1 << r);
                    pc[j] = keep + recv;
                }
            }
        }
        float cval = pc[0] + __shfl_xor_sync(0xffffffffu, pc[0], 16);
        if (lane < 16) {
            int i = ((lane & 1) << 3) | (((lane >> 1) & 1) << 2)
                  | (((lane >> 2) & 1) << 1) | ((lane >> 3) & 1);
            const int c = h * 16 + i;
            out[row * 128 + c] = cval + b_prj[c];
        }
    }
}

// ---------------------------------------------------------------------------
extern "C" void kernel_launch(void* const* d_in, const int* in_sizes, int n_in,
                              void* d_out, int out_size) {
    const float* x     = (const float*)d_in[0];
    const float* e     = (const float*)d_in[1];
    const float* w_qkv = (const float*)d_in[2];
    const float* w_ekv = (const float*)d_in[3];
    const float* b_ekv = (const float*)d_in[4];
    const float* w_prj = (const float*)d_in[5];
    const float* b_prj = (const float*)d_in[6];
    float* out = (float*)d_out;

    cudaFuncSetAttribute((const void*)qv_kernel,
                         cudaFuncAttributeMaxDynamicSharedMemorySize, QV_SMEM_BYTES);

    qv_kernel       <<<dim3(4, 32), 128, QV_SMEM_BYTES>>>(x, w_qkv);
    attn_proj_kernel<<<ROWS_,       256>>>(e, w_ekv, b_ekv, w_prj, b_prj, out);
}